// round 2
// baseline (speedup 1.0000x reference)
#include <cuda_runtime.h>
#include <cuda_bf16.h>
#include <cstdint>
#include <cstddef>

// ---------------------------------------------------------------------------
// ContentContrastiveLoss on GB300 (sm_103a, compiled via bare sm_103 -> no
// tcgen05 in this pipeline; use classic mma.sync HMMA path instead).
//   loss = ( sum_offdiag max(0.2 - ||ci-aj||,0)^2 + sum_i ||ci-ai||^2 ) / (2N)
//   rows L2-normalized ==> ||ci-aj||^2 = max(2 - 2 <ci,aj>, 0)
// ---------------------------------------------------------------------------

#define NROWS 2048
#define DIM   8192
#define TILE  128
#define KC    32          // K elements per chunk (bf16)
#define SSTR  40          // smem row stride in bf16 elems (80B, conflict-free)

__device__ __nv_bfloat16 g_Cn[(size_t)NROWS * DIM];
__device__ __nv_bfloat16 g_An[(size_t)NROWS * DIM];
__device__ double g_acc;

__device__ __forceinline__ uint32_t smem_u32(const void* p) {
    return (uint32_t)__cvta_generic_to_shared(p);
}

__device__ __forceinline__ void cp_async16(uint32_t dst, const void* src) {
    asm volatile("cp.async.cg.shared.global [%0], [%1], 16;"
                 :: "r"(dst), "l"(src));
}
__device__ __forceinline__ void cp_commit() {
    asm volatile("cp.async.commit_group;");
}
template <int N>
__device__ __forceinline__ void cp_wait() {
    asm volatile("cp.async.wait_group %0;" :: "n"(N));
}

__device__ __forceinline__ void ldsm_x4(uint32_t (&r)[4], uint32_t addr) {
    asm volatile("ldmatrix.sync.aligned.m8n8.x4.shared.b16 {%0,%1,%2,%3}, [%4];"
                 : "=r"(r[0]), "=r"(r[1]), "=r"(r[2]), "=r"(r[3]) : "r"(addr));
}

__device__ __forceinline__ void mma_bf16(float (&d)[4], const uint32_t (&a)[4],
                                         const uint32_t b0, const uint32_t b1) {
    asm volatile(
        "mma.sync.aligned.m16n8k16.row.col.f32.bf16.bf16.f32 "
        "{%0,%1,%2,%3}, {%4,%5,%6,%7}, {%8,%9}, {%0,%1,%2,%3};"
        : "+f"(d[0]), "+f"(d[1]), "+f"(d[2]), "+f"(d[3])
        : "r"(a[0]), "r"(a[1]), "r"(a[2]), "r"(a[3]), "r"(b0), "r"(b1));
}

// ---------------------------------------------------------------------------
// Kernel 1: row L2-normalize fp32 -> bf16. Block (0,0) also zeroes g_acc.
// ---------------------------------------------------------------------------
__global__ void __launch_bounds__(256) normalize_kernel(
    const float* __restrict__ C, const float* __restrict__ A) {
    __shared__ float red[8];
    const int row   = blockIdx.x;
    const int which = blockIdx.y;
    const int tid   = threadIdx.x;
    if (row == 0 && which == 0 && tid == 0) g_acc = 0.0;

    const float4* src = (const float4*)((which ? A : C) + (size_t)row * DIM);
    uint2* dst = (uint2*)((which ? g_An : g_Cn) + (size_t)row * DIM);

    float4 v[8];
    float s = 0.0f;
#pragma unroll
    for (int i = 0; i < 8; i++) {
        v[i] = src[tid + i * 256];
        s += v[i].x * v[i].x + v[i].y * v[i].y + v[i].z * v[i].z + v[i].w * v[i].w;
    }
#pragma unroll
    for (int o = 16; o; o >>= 1) s += __shfl_down_sync(0xFFFFFFFFu, s, o);
    if ((tid & 31) == 0) red[tid >> 5] = s;
    __syncthreads();
    float tot = 0.0f;
#pragma unroll
    for (int i = 0; i < 8; i++) tot += red[i];
    const float inv = 1.0f / fmaxf(sqrtf(tot), 1e-12f);

#pragma unroll
    for (int i = 0; i < 8; i++) {
        __nv_bfloat162 lo = __floats2bfloat162_rn(v[i].x * inv, v[i].y * inv);
        __nv_bfloat162 hi = __floats2bfloat162_rn(v[i].z * inv, v[i].w * inv);
        uint2 p;
        p.x = *reinterpret_cast<uint32_t*>(&lo);
        p.y = *reinterpret_cast<uint32_t*>(&hi);
        dst[tid + i * 256] = p;
    }
}

// ---------------------------------------------------------------------------
// Kernel 2: 128x128-tile bf16 HMMA GEMM with fused loss epilogue.
//   grid (16,16), 256 threads (8 warps, 4 warp-rows x 2 warp-cols).
//   Warp tile 32x64 = 2 m-frags x 8 n-frags of m16n8k16.
//   Double-buffered cp.async K-chunks of 32.
// ---------------------------------------------------------------------------
__global__ void __launch_bounds__(256) gemm_loss_kernel() {
    __shared__ __align__(16) __nv_bfloat16 sA[2][TILE * SSTR];
    __shared__ __align__(16) __nv_bfloat16 sB[2][TILE * SSTR];

    const int tid    = threadIdx.x;
    const int wid    = tid >> 5;
    const int lane   = tid & 31;
    const int warp_m = wid & 3;   // 0..3 -> 32-row strip
    const int warp_n = wid >> 2;  // 0..1 -> 64-col strip

    const int ti = blockIdx.y;
    const int tj = blockIdx.x;
    const __nv_bfloat16* __restrict__ Ab = g_Cn + (size_t)ti * TILE * DIM;
    const __nv_bfloat16* __restrict__ Bb = g_An + (size_t)tj * TILE * DIM;

    // ---- global->shared task map: 1024 16B segments per chunk, 4/thread ----
    int t_which[4], t_row[4], t_seg[4];
    const __nv_bfloat16* t_src[4];
#pragma unroll
    for (int t = 0; t < 4; t++) {
        const int task = tid + t * 256;
        t_which[t] = task >> 9;
        t_row[t]   = (task >> 2) & 127;
        t_seg[t]   = task & 3;
        t_src[t]   = (t_which[t] ? Bb : Ab) + (size_t)t_row[t] * DIM + t_seg[t] * 8;
    }
    uint32_t t_dst[4];
#pragma unroll
    for (int t = 0; t < 4; t++) {
        const __nv_bfloat16* base = t_which[t] ? &sB[0][0] : &sA[0][0];
        t_dst[t] = smem_u32(base + t_row[t] * SSTR + t_seg[t] * 8);
    }
    const uint32_t buf_bytes = TILE * SSTR * sizeof(__nv_bfloat16);

    // ---- ldmatrix source addresses (per buffer 0; add buf offset later) ----
    // A frags: 16x16 tiles. row = warp_m*32 + mf*16 + (lane&15), col8 = lane>>4
    uint32_t aAddr[2];
#pragma unroll
    for (int mf = 0; mf < 2; mf++) {
        const int r = warp_m * 32 + mf * 16 + (lane & 15);
        const int c = (lane >> 4) * 8;
        aAddr[mf] = smem_u32(&sA[0][0] + r * SSTR + c);
    }
    // B frag pairs: 16 n-rows x 16 k. row = warp_n*64 + p*16 + (lane&7) +
    // ((lane>>4)&1)*8 ; col8 = (lane>>3)&1
    uint32_t bAddr[4];
#pragma unroll
    for (int p = 0; p < 4; p++) {
        const int r = warp_n * 64 + p * 16 + (lane & 7) + ((lane >> 4) & 1) * 8;
        const int c = ((lane >> 3) & 1) * 8;
        bAddr[p] = smem_u32(&sB[0][0] + r * SSTR + c);
    }

    float acc[2][8][4];
#pragma unroll
    for (int mf = 0; mf < 2; mf++)
#pragma unroll
        for (int nf = 0; nf < 8; nf++)
#pragma unroll
            for (int e = 0; e < 4; e++) acc[mf][nf][e] = 0.0f;

    // ---- prologue: load chunk 0 into buffer 0 ----
#pragma unroll
    for (int t = 0; t < 4; t++) cp_async16(t_dst[t], t_src[t]);
    cp_commit();

    const int NCHUNK = DIM / KC;  // 256
    for (int k0 = 0; k0 < NCHUNK; k0++) {
        const uint32_t cur = (uint32_t)(k0 & 1) * buf_bytes;
        if (k0 + 1 < NCHUNK) {
            const uint32_t nxt = (uint32_t)((k0 + 1) & 1) * buf_bytes;
            const int koff = (k0 + 1) * KC;
#pragma unroll
            for (int t = 0; t < 4; t++)
                cp_async16(t_dst[t] + nxt, t_src[t] + koff);
            cp_commit();
            cp_wait<1>();
        } else {
            cp_wait<0>();
        }
        __syncthreads();

#pragma unroll
        for (int ks = 0; ks < 2; ks++) {  // two k16 steps per 32-chunk
            uint32_t a[2][4];
#pragma unroll
            for (int mf = 0; mf < 2; mf++)
                ldsm_x4(a[mf], aAddr[mf] + cur + ks * 32);  // 16 bf16 = 32B
            uint32_t b[8][2];
#pragma unroll
            for (int p = 0; p < 4; p++) {
                uint32_t r4[4];
                ldsm_x4(r4, bAddr[p] + cur + ks * 32);
                b[2 * p][0]     = r4[0];
                b[2 * p][1]     = r4[1];
                b[2 * p + 1][0] = r4[2];
                b[2 * p + 1][1] = r4[3];
            }
#pragma unroll
            for (int mf = 0; mf < 2; mf++)
#pragma unroll
                for (int nf = 0; nf < 8; nf++)
                    mma_bf16(acc[mf][nf], a[mf], b[nf][0], b[nf][1]);
        }
        __syncthreads();  // all warps done with 'cur' before it is refilled
    }

    // ---- fused loss epilogue on register accumulators ----
    float lsum = 0.0f;
#pragma unroll
    for (int mf = 0; mf < 2; mf++) {
        const int gm = ti * TILE + warp_m * 32 + mf * 16 + (lane >> 2);
#pragma unroll
        for (int nf = 0; nf < 8; nf++) {
            const int gn = tj * TILE + warp_n * 64 + nf * 8 + (lane & 3) * 2;
#pragma unroll
            for (int e = 0; e < 4; e++) {
                const int gi = gm + (e >> 1) * 8;
                const int gj = gn + (e & 1);
                const float s  = acc[mf][nf][e];
                const float d2 = fmaxf(2.0f - 2.0f * s, 0.0f);
                if (gi == gj) {
                    lsum += d2;  // diagonal distance squared
                } else {
                    const float diff = 0.2f - sqrtf(d2);
                    if (diff > 0.0f) lsum += diff * diff;
                }
            }
        }
    }
#pragma unroll
    for (int o = 16; o; o >>= 1) lsum += __shfl_down_sync(0xFFFFFFFFu, lsum, o);
    if (lane == 0) atomicAdd(&g_acc, (double)lsum);
}

// ---------------------------------------------------------------------------
// Kernel 3: finalize scalar loss.
// ---------------------------------------------------------------------------
__global__ void finalize_kernel(float* out) {
    out[0] = (float)(g_acc * (1.0 / (2.0 * (double)NROWS)));
}

extern "C" void kernel_launch(void* const* d_in, const int* in_sizes, int n_in,
                              void* d_out, int out_size) {
    (void)in_sizes; (void)n_in; (void)out_size;
    const float* C = (const float*)d_in[0];  // content_code
    const float* A = (const float*)d_in[1];  // audio_feature

    normalize_kernel<<<dim3(NROWS, 2), 256>>>(C, A);
    gemm_loss_kernel<<<dim3(NROWS / TILE, NROWS / TILE), 256>>>();
    finalize_kernel<<<1, 1>>>((float*)d_out);
}

// round 3
// speedup vs baseline: 1.0293x; 1.0293x over previous
#include <cuda_runtime.h>
#include <cuda_bf16.h>
#include <cstdint>
#include <cstddef>

// ---------------------------------------------------------------------------
// ContentContrastiveLoss on GB300 (sm_103 target -> no tcgen05; use mma.sync).
// Round 3: FP8 e4m3 QMMA m16n8k32 (2x FLOP/inst vs bf16 m16n8k16).
//   rows L2-normalized, scaled by S=64, quantized to e4m3.
//   sim = dot_fp8 / S^2 ;  ||ci-aj||^2 = max(2 - 2 sim, 0)
//   loss = ( sum_offdiag max(0.2-dist,0)^2 + sum_i dist_ii^2 ) / (2N)
// ---------------------------------------------------------------------------

#define NROWS 2048
#define DIM   8192
#define TILE  128
#define KCB   64          // K bytes (fp8 elems) per chunk
#define SSTR  80          // smem row stride in BYTES (64 data + 16 pad)

__device__ uint8_t g_Cn[(size_t)NROWS * DIM];   // e4m3, scaled by 64
__device__ uint8_t g_An[(size_t)NROWS * DIM];
__device__ double g_acc;

__device__ __forceinline__ uint32_t smem_u32(const void* p) {
    return (uint32_t)__cvta_generic_to_shared(p);
}

__device__ __forceinline__ void cp_async16(uint32_t dst, const void* src) {
    asm volatile("cp.async.cg.shared.global [%0], [%1], 16;"
                 :: "r"(dst), "l"(src));
}
__device__ __forceinline__ void cp_commit() {
    asm volatile("cp.async.commit_group;");
}
template <int N>
__device__ __forceinline__ void cp_wait() {
    asm volatile("cp.async.wait_group %0;" :: "n"(N));
}

__device__ __forceinline__ void ldsm_x4(uint32_t (&r)[4], uint32_t addr) {
    asm volatile("ldmatrix.sync.aligned.m8n8.x4.shared.b16 {%0,%1,%2,%3}, [%4];"
                 : "=r"(r[0]), "=r"(r[1]), "=r"(r[2]), "=r"(r[3]) : "r"(addr));
}

__device__ __forceinline__ void mma_fp8(float (&d)[4], const uint32_t (&a)[4],
                                        const uint32_t b0, const uint32_t b1) {
    asm volatile(
        "mma.sync.aligned.m16n8k32.row.col.f32.e4m3.e4m3.f32 "
        "{%0,%1,%2,%3}, {%4,%5,%6,%7}, {%8,%9}, {%0,%1,%2,%3};"
        : "+f"(d[0]), "+f"(d[1]), "+f"(d[2]), "+f"(d[3])
        : "r"(a[0]), "r"(a[1]), "r"(a[2]), "r"(a[3]), "r"(b0), "r"(b1));
}

// pack 4 floats -> 4 e4m3 bytes (x,y = low pair)
__device__ __forceinline__ uint32_t pack_e4m3x4(float x, float y, float z, float w) {
    uint16_t lo, hi;
    asm("cvt.rn.satfinite.e4m3x2.f32 %0, %1, %2;" : "=h"(lo) : "f"(y), "f"(x));
    asm("cvt.rn.satfinite.e4m3x2.f32 %0, %1, %2;" : "=h"(hi) : "f"(w), "f"(z));
    return (uint32_t)lo | ((uint32_t)hi << 16);
}

// ---------------------------------------------------------------------------
// Kernel 1: row L2-normalize fp32 -> e4m3 (scale 64). Block(0,0) zeroes g_acc.
// ---------------------------------------------------------------------------
__global__ void __launch_bounds__(256) normalize_kernel(
    const float* __restrict__ C, const float* __restrict__ A) {
    __shared__ float red[8];
    const int row   = blockIdx.x;
    const int which = blockIdx.y;
    const int tid   = threadIdx.x;
    if (row == 0 && which == 0 && tid == 0) g_acc = 0.0;

    const float4* src = (const float4*)((which ? A : C) + (size_t)row * DIM);
    uint32_t* dst = (uint32_t*)((which ? g_An : g_Cn) + (size_t)row * DIM);

    float4 v[8];
    float s = 0.0f;
#pragma unroll
    for (int i = 0; i < 8; i++) {
        v[i] = src[tid + i * 256];
        s += v[i].x * v[i].x + v[i].y * v[i].y + v[i].z * v[i].z + v[i].w * v[i].w;
    }
#pragma unroll
    for (int o = 16; o; o >>= 1) s += __shfl_down_sync(0xFFFFFFFFu, s, o);
    if ((tid & 31) == 0) red[tid >> 5] = s;
    __syncthreads();
    float tot = 0.0f;
#pragma unroll
    for (int i = 0; i < 8; i++) tot += red[i];
    const float inv = 64.0f / fmaxf(sqrtf(tot), 1e-12f);  // scale S=64 folded in

#pragma unroll
    for (int i = 0; i < 8; i++) {
        dst[tid + i * 256] =
            pack_e4m3x4(v[i].x * inv, v[i].y * inv, v[i].z * inv, v[i].w * inv);
    }
}

// ---------------------------------------------------------------------------
// Kernel 2: 128x128-tile FP8 QMMA GEMM with fused loss epilogue.
//   grid (16,16), 256 threads (8 warps, 4 warp-rows x 2 warp-cols).
//   Warp tile 32x64 = 2 m-frags x 8 n-frags of m16n8k32.
//   Double-buffered cp.async K-chunks of 64 fp8.
// ---------------------------------------------------------------------------
__global__ void __launch_bounds__(256) gemm_loss_kernel() {
    __shared__ __align__(16) uint8_t sA[2][TILE * SSTR];
    __shared__ __align__(16) uint8_t sB[2][TILE * SSTR];

    const int tid    = threadIdx.x;
    const int wid    = tid >> 5;
    const int lane   = tid & 31;
    const int warp_m = wid & 3;   // 0..3 -> 32-row strip
    const int warp_n = wid >> 2;  // 0..1 -> 64-col strip

    const int ti = blockIdx.y;
    const int tj = blockIdx.x;
    const uint8_t* __restrict__ Ab = g_Cn + (size_t)ti * TILE * DIM;
    const uint8_t* __restrict__ Bb = g_An + (size_t)tj * TILE * DIM;

    // ---- global->shared task map: 2 tiles x 128 rows x 4 segs(16B) = 1024 ----
    const uint8_t* t_src[4];
    uint32_t t_dst[4];
#pragma unroll
    for (int t = 0; t < 4; t++) {
        const int task  = tid + t * 256;
        const int which = task >> 9;
        const int r     = (task >> 2) & 127;
        const int seg   = task & 3;
        t_src[t] = (which ? Bb : Ab) + (size_t)r * DIM + seg * 16;
        t_dst[t] = smem_u32((which ? &sB[0][0] : &sA[0][0]) + r * SSTR + seg * 16);
    }
    const uint32_t buf_bytes = TILE * SSTR;

    // ---- ldmatrix addresses (buffer 0; byte offsets) ----
    // A: row = warp_m*32 + mf*16 + (lane&15); col16B = (lane>>4)
    uint32_t aAddr[2];
#pragma unroll
    for (int mf = 0; mf < 2; mf++) {
        const int r = warp_m * 32 + mf * 16 + (lane & 15);
        aAddr[mf] = smem_u32(&sA[0][0] + r * SSTR + (lane >> 4) * 16);
    }
    // B: row = warp_n*64 + p*16 + (lane&7) + ((lane>>4)&1)*8; col16B=(lane>>3)&1
    uint32_t bAddr[4];
#pragma unroll
    for (int p = 0; p < 4; p++) {
        const int r = warp_n * 64 + p * 16 + (lane & 7) + ((lane >> 4) & 1) * 8;
        bAddr[p] = smem_u32(&sB[0][0] + r * SSTR + ((lane >> 3) & 1) * 16);
    }

    float acc[2][8][4];
#pragma unroll
    for (int mf = 0; mf < 2; mf++)
#pragma unroll
        for (int nf = 0; nf < 8; nf++)
#pragma unroll
            for (int e = 0; e < 4; e++) acc[mf][nf][e] = 0.0f;

    // ---- prologue: chunk 0 -> buffer 0 ----
#pragma unroll
    for (int t = 0; t < 4; t++) cp_async16(t_dst[t], t_src[t]);
    cp_commit();

    const int NCHUNK = DIM / KCB;  // 128
    for (int k0 = 0; k0 < NCHUNK; k0++) {
        const uint32_t cur = (uint32_t)(k0 & 1) * buf_bytes;
        if (k0 + 1 < NCHUNK) {
            const uint32_t nxt = (uint32_t)((k0 + 1) & 1) * buf_bytes;
            const int koff = (k0 + 1) * KCB;
#pragma unroll
            for (int t = 0; t < 4; t++)
                cp_async16(t_dst[t] + nxt, t_src[t] + koff);
            cp_commit();
            cp_wait<1>();
        } else {
            cp_wait<0>();
        }
        __syncthreads();

#pragma unroll
        for (int ks = 0; ks < 2; ks++) {  // two k32 steps per 64B chunk
            uint32_t a[2][4];
#pragma unroll
            for (int mf = 0; mf < 2; mf++)
                ldsm_x4(a[mf], aAddr[mf] + cur + ks * 32);  // 32 fp8 = 32B
            uint32_t b[8][2];
#pragma unroll
            for (int p = 0; p < 4; p++) {
                uint32_t r4[4];
                ldsm_x4(r4, bAddr[p] + cur + ks * 32);
                b[2 * p][0]     = r4[0];
                b[2 * p][1]     = r4[1];
                b[2 * p + 1][0] = r4[2];
                b[2 * p + 1][1] = r4[3];
            }
#pragma unroll
            for (int mf = 0; mf < 2; mf++)
#pragma unroll
                for (int nf = 0; nf < 8; nf++)
                    mma_fp8(acc[mf][nf], a[mf], b[nf][0], b[nf][1]);
        }
        __syncthreads();  // all warps done with 'cur' before it is refilled
    }

    // ---- fused loss epilogue; undo S^2 = 4096 quantization scale ----
    constexpr float INV_S2 = 1.0f / 4096.0f;
    float lsum = 0.0f;
#pragma unroll
    for (int mf = 0; mf < 2; mf++) {
        const int gm = ti * TILE + warp_m * 32 + mf * 16 + (lane >> 2);
#pragma unroll
        for (int nf = 0; nf < 8; nf++) {
            const int gn = tj * TILE + warp_n * 64 + nf * 8 + (lane & 3) * 2;
#pragma unroll
            for (int e = 0; e < 4; e++) {
                const int gi = gm + (e >> 1) * 8;
                const int gj = gn + (e & 1);
                const float s  = acc[mf][nf][e] * INV_S2;
                const float d2 = fmaxf(2.0f - 2.0f * s, 0.0f);
                if (gi == gj) {
                    lsum += d2;  // diagonal distance squared
                } else {
                    const float diff = 0.2f - sqrtf(d2);
                    if (diff > 0.0f) lsum += diff * diff;
                }
            }
        }
    }
#pragma unroll
    for (int o = 16; o; o >>= 1) lsum += __shfl_down_sync(0xFFFFFFFFu, lsum, o);
    if (lane == 0) atomicAdd(&g_acc, (double)lsum);
}

// ---------------------------------------------------------------------------
// Kernel 3: finalize scalar loss.
// ---------------------------------------------------------------------------
__global__ void finalize_kernel(float* out) {
    out[0] = (float)(g_acc * (1.0 / (2.0 * (double)NROWS)));
}

extern "C" void kernel_launch(void* const* d_in, const int* in_sizes, int n_in,
                              void* d_out, int out_size) {
    (void)in_sizes; (void)n_in; (void)out_size;
    const float* C = (const float*)d_in[0];  // content_code
    const float* A = (const float*)d_in[1];  // audio_feature

    normalize_kernel<<<dim3(NROWS, 2), 256>>>(C, A);
    gemm_loss_kernel<<<dim3(NROWS / TILE, NROWS / TILE), 256>>>();
    finalize_kernel<<<1, 1>>>((float*)d_out);
}

// round 4
// speedup vs baseline: 4.1102x; 3.9931x over previous
#include <cuda_runtime.h>
#include <cuda_bf16.h>
#include <cstdint>
#include <cstddef>

// ---------------------------------------------------------------------------
// ContentContrastiveLoss, GB300 (sm_103 target: mma.sync only, no tcgen05).
// Round 4: algorithmic FLOP cut.
//   loss = ( sum_offdiag max(0.2-||ci-aj||,0)^2 + sum_i ||ci-ai||^2 ) / (2N)
// Hinge active only if sim > 0.98. Cauchy-Schwarz screen:
//   sim <= head_dot(1024 dims) + rc_i * ra_j   (tail norms)
// -> bf16 N^2 x 1024 GEMM flags candidates (expected: none); exact fp32
//    fallback computes the hinge for flagged pairs. Diagonal computed exactly
//    in fp32 inside the normalize kernel.
// ---------------------------------------------------------------------------

#define NROWS 2048
#define DIM   8192
#define HEAD  1024
#define TILE  128
#define KC    32          // bf16 K elems per GEMM chunk
#define SSTR  40          // smem row stride in bf16 elems (80B)
#define FCAP  65536

__device__ __nv_bfloat16 g_Ch[(size_t)NROWS * HEAD];  // normalized heads
__device__ __nv_bfloat16 g_Ah[(size_t)NROWS * HEAD];
__device__ float  g_rc[NROWS];      // tail-norm fraction of C rows
__device__ float  g_ra[NROWS];
__device__ float  g_invC[NROWS];    // 1/max(||c||,eps)
__device__ float  g_invA[NROWS];
__device__ float  g_d2[NROWS];      // exact diagonal dist^2
__device__ int    g_nflag;          // flagged-pair count (reset by finalize)
__device__ int2   g_flags[FCAP];
__device__ double g_acc;            // hinge accumulator (reset by finalize)

__device__ __forceinline__ uint32_t smem_u32(const void* p) {
    return (uint32_t)__cvta_generic_to_shared(p);
}
__device__ __forceinline__ void cp_async16(uint32_t dst, const void* src) {
    asm volatile("cp.async.cg.shared.global [%0], [%1], 16;" :: "r"(dst), "l"(src));
}
__device__ __forceinline__ void cp_commit() { asm volatile("cp.async.commit_group;"); }
template <int N>
__device__ __forceinline__ void cp_wait() {
    asm volatile("cp.async.wait_group %0;" :: "n"(N));
}
__device__ __forceinline__ void ldsm_x4(uint32_t (&r)[4], uint32_t addr) {
    asm volatile("ldmatrix.sync.aligned.m8n8.x4.shared.b16 {%0,%1,%2,%3}, [%4];"
                 : "=r"(r[0]), "=r"(r[1]), "=r"(r[2]), "=r"(r[3]) : "r"(addr));
}
__device__ __forceinline__ void mma_bf16(float (&d)[4], const uint32_t (&a)[4],
                                         const uint32_t b0, const uint32_t b1) {
    asm volatile(
        "mma.sync.aligned.m16n8k16.row.col.f32.bf16.bf16.f32 "
        "{%0,%1,%2,%3}, {%4,%5,%6,%7}, {%8,%9}, {%0,%1,%2,%3};"
        : "+f"(d[0]), "+f"(d[1]), "+f"(d[2]), "+f"(d[3])
        : "r"(a[0]), "r"(a[1]), "r"(a[2]), "r"(a[3]), "r"(b0), "r"(b1));
}
__device__ __forceinline__ float dot4(const float4 a, const float4 b) {
    return a.x * b.x + a.y * b.y + a.z * b.z + a.w * b.w;
}

// ---------------------------------------------------------------------------
// Kernel 1: per-row (block = row): norms of C and A, exact fp32 diag dot,
// bf16 normalized heads, tail-norm fractions.
// ---------------------------------------------------------------------------
__global__ void __launch_bounds__(256) normalize_kernel(
    const float* __restrict__ C, const float* __restrict__ A) {
    __shared__ float red[8][5];
    const int row = blockIdx.x;
    const int tid = threadIdx.x;

    const float4* cs = (const float4*)(C + (size_t)row * DIM);
    const float4* as = (const float4*)(A + (size_t)row * DIM);

    float4 cv[8], av[8];
    float sC = 0.f, sA = 0.f, sD = 0.f;
#pragma unroll
    for (int i = 0; i < 8; i++) {
        cv[i] = cs[tid + i * 256];
        av[i] = as[tid + i * 256];
        sC += dot4(cv[i], cv[i]);
        sA += dot4(av[i], av[i]);
        sD += dot4(cv[i], av[i]);
    }
    // head (first 1024 elems) energy = the i==0 chunk
    float hC = dot4(cv[0], cv[0]);
    float hA = dot4(av[0], av[0]);

    float v5[5] = {sC, sA, sD, hC, hA};
#pragma unroll
    for (int j = 0; j < 5; j++)
#pragma unroll
        for (int o = 16; o; o >>= 1)
            v5[j] += __shfl_down_sync(0xFFFFFFFFu, v5[j], o);
    if ((tid & 31) == 0)
#pragma unroll
        for (int j = 0; j < 5; j++) red[tid >> 5][j] = v5[j];
    __syncthreads();
    float tC = 0.f, tA = 0.f, tD = 0.f, tHC = 0.f, tHA = 0.f;
#pragma unroll
    for (int w = 0; w < 8; w++) {
        tC += red[w][0]; tA += red[w][1]; tD += red[w][2];
        tHC += red[w][3]; tHA += red[w][4];
    }
    const float invC = 1.0f / fmaxf(sqrtf(tC), 1e-12f);
    const float invA = 1.0f / fmaxf(sqrtf(tA), 1e-12f);

    if (tid == 0) {
        const float sim = tD * invC * invA;
        g_d2[row]   = fmaxf(2.0f - 2.0f * sim, 0.0f);
        g_invC[row] = invC;
        g_invA[row] = invA;
        g_rc[row] = sqrtf(fmaxf(1.0f - tHC * invC * invC, 0.0f));
        g_ra[row] = sqrtf(fmaxf(1.0f - tHA * invA * invA, 0.0f));
    }

    // write bf16 normalized heads (elements 4*tid .. 4*tid+3)
    {
        __nv_bfloat162 lo = __floats2bfloat162_rn(cv[0].x * invC, cv[0].y * invC);
        __nv_bfloat162 hi = __floats2bfloat162_rn(cv[0].z * invC, cv[0].w * invC);
        uint2 p;
        p.x = *reinterpret_cast<uint32_t*>(&lo);
        p.y = *reinterpret_cast<uint32_t*>(&hi);
        ((uint2*)(g_Ch + (size_t)row * HEAD))[tid] = p;
    }
    {
        __nv_bfloat162 lo = __floats2bfloat162_rn(av[0].x * invA, av[0].y * invA);
        __nv_bfloat162 hi = __floats2bfloat162_rn(av[0].z * invA, av[0].w * invA);
        uint2 p;
        p.x = *reinterpret_cast<uint32_t*>(&lo);
        p.y = *reinterpret_cast<uint32_t*>(&hi);
        ((uint2*)(g_Ah + (size_t)row * HEAD))[tid] = p;
    }
}

// ---------------------------------------------------------------------------
// Kernel 2: 128x128-tile bf16 HMMA screen GEMM over K=HEAD.
// Epilogue flags pairs whose Cauchy-Schwarz upper bound can reach the margin.
// ---------------------------------------------------------------------------
__global__ void __launch_bounds__(256) screen_gemm_kernel() {
    __shared__ __align__(16) __nv_bfloat16 sA[2][TILE * SSTR];
    __shared__ __align__(16) __nv_bfloat16 sB[2][TILE * SSTR];
    __shared__ float rcS[TILE], raS[TILE];

    const int tid    = threadIdx.x;
    const int wid    = tid >> 5;
    const int lane   = tid & 31;
    const int warp_m = wid & 3;
    const int warp_n = wid >> 2;

    const int ti = blockIdx.y;
    const int tj = blockIdx.x;
    const __nv_bfloat16* __restrict__ Ab = g_Ch + (size_t)ti * TILE * HEAD;
    const __nv_bfloat16* __restrict__ Bb = g_Ah + (size_t)tj * TILE * HEAD;

    // global->shared tasks: 2 tiles x 128 rows x 4 segs(16B) = 1024, 4/thread
    const __nv_bfloat16* t_src[4];
    uint32_t t_dst[4];
#pragma unroll
    for (int t = 0; t < 4; t++) {
        const int task  = tid + t * 256;
        const int which = task >> 9;
        const int r     = (task >> 2) & 127;
        const int seg   = task & 3;
        t_src[t] = (which ? Bb : Ab) + (size_t)r * HEAD + seg * 8;
        t_dst[t] = smem_u32((which ? &sB[0][0] : &sA[0][0]) + r * SSTR + seg * 8);
    }
    const uint32_t buf_bytes = TILE * SSTR * sizeof(__nv_bfloat16);

    uint32_t aAddr[2];
#pragma unroll
    for (int mf = 0; mf < 2; mf++) {
        const int r = warp_m * 32 + mf * 16 + (lane & 15);
        aAddr[mf] = smem_u32(&sA[0][0] + r * SSTR + (lane >> 4) * 8);
    }
    uint32_t bAddr[4];
#pragma unroll
    for (int p = 0; p < 4; p++) {
        const int r = warp_n * 64 + p * 16 + (lane & 7) + ((lane >> 4) & 1) * 8;
        bAddr[p] = smem_u32(&sB[0][0] + r * SSTR + ((lane >> 3) & 1) * 8);
    }

    float acc[2][8][4];
#pragma unroll
    for (int mf = 0; mf < 2; mf++)
#pragma unroll
        for (int nf = 0; nf < 8; nf++)
#pragma unroll
            for (int e = 0; e < 4; e++) acc[mf][nf][e] = 0.0f;

    if (tid < TILE) rcS[tid] = g_rc[ti * TILE + tid];
    else            raS[tid - TILE] = g_ra[tj * TILE + (tid - TILE)];

#pragma unroll
    for (int t = 0; t < 4; t++) cp_async16(t_dst[t], t_src[t]);
    cp_commit();

    const int NCHUNK = HEAD / KC;  // 32
    for (int k0 = 0; k0 < NCHUNK; k0++) {
        const uint32_t cur = (uint32_t)(k0 & 1) * buf_bytes;
        if (k0 + 1 < NCHUNK) {
            const uint32_t nxt = (uint32_t)((k0 + 1) & 1) * buf_bytes;
            const int koff = (k0 + 1) * KC;
#pragma unroll
            for (int t = 0; t < 4; t++) cp_async16(t_dst[t] + nxt, t_src[t] + koff);
            cp_commit();
            cp_wait<1>();
        } else {
            cp_wait<0>();
        }
        __syncthreads();

#pragma unroll
        for (int ks = 0; ks < 2; ks++) {
            uint32_t a[2][4];
#pragma unroll
            for (int mf = 0; mf < 2; mf++)
                ldsm_x4(a[mf], aAddr[mf] + cur + ks * 32);
            uint32_t b[8][2];
#pragma unroll
            for (int p = 0; p < 4; p++) {
                uint32_t r4[4];
                ldsm_x4(r4, bAddr[p] + cur + ks * 32);
                b[2 * p][0]     = r4[0];
                b[2 * p][1]     = r4[1];
                b[2 * p + 1][0] = r4[2];
                b[2 * p + 1][1] = r4[3];
            }
#pragma unroll
            for (int mf = 0; mf < 2; mf++)
#pragma unroll
                for (int nf = 0; nf < 8; nf++)
                    mma_bf16(acc[mf][nf], a[mf], b[nf][0], b[nf][1]);
        }
        __syncthreads();
    }

    // ---- screen epilogue: flag pairs whose upper bound can hit sim > 0.98 ----
    // true sim <= head_dot + rc*ra <= (s + 0.004 bf16 err) + rc*ra;
    // flag if s + rc*ra > 0.97 (0.01 total slack).
#pragma unroll
    for (int mf = 0; mf < 2; mf++) {
#pragma unroll
        for (int nf = 0; nf < 8; nf++) {
#pragma unroll
            for (int e = 0; e < 4; e++) {
                const int li = warp_m * 32 + mf * 16 + (lane >> 2) + (e >> 1) * 8;
                const int lj = warp_n * 64 + nf * 8 + (lane & 3) * 2 + (e & 1);
                const int gi = ti * TILE + li;
                const int gj = tj * TILE + lj;
                if (gi == gj) continue;  // diagonal handled exactly elsewhere
                const float bound = acc[mf][nf][e] + rcS[li] * raS[lj];
                if (bound > 0.97f) {
                    const int idx = atomicAdd(&g_nflag, 1);
                    if (idx < FCAP) g_flags[idx] = make_int2(gi, gj);
                }
            }
        }
    }
}

// ---------------------------------------------------------------------------
// Kernel 3: exact fp32 hinge for flagged pairs (expected: zero pairs).
// ---------------------------------------------------------------------------
__global__ void __launch_bounds__(256) fallback_kernel(
    const float* __restrict__ C, const float* __restrict__ A) {
    __shared__ float red[8];
    const int tid = threadIdx.x;
    const int total = min(g_nflag, FCAP);
    for (int p = blockIdx.x; p < total; p += gridDim.x) {
        const int2 pr = g_flags[p];
        const float4* c = (const float4*)(C + (size_t)pr.x * DIM);
        const float4* a = (const float4*)(A + (size_t)pr.y * DIM);
        float s = 0.f;
        for (int i = tid; i < DIM / 4; i += 256) s += dot4(c[i], a[i]);
#pragma unroll
        for (int o = 16; o; o >>= 1) s += __shfl_down_sync(0xFFFFFFFFu, s, o);
        if ((tid & 31) == 0) red[tid >> 5] = s;
        __syncthreads();
        if (tid == 0) {
            float tot = 0.f;
#pragma unroll
            for (int w = 0; w < 8; w++) tot += red[w];
            const float sim  = tot * g_invC[pr.x] * g_invA[pr.y];
            const float dist = sqrtf(fmaxf(2.0f - 2.0f * sim, 0.0f));
            const float diff = 0.2f - dist;
            if (diff > 0.0f) atomicAdd(&g_acc, (double)(diff * diff));
        }
        __syncthreads();
    }
}

// ---------------------------------------------------------------------------
// Kernel 4: finalize = (sum diag d2 + hinge acc)/(2N); reset state for replay.
// ---------------------------------------------------------------------------
__global__ void __launch_bounds__(256) finalize_kernel(float* out) {
    __shared__ double red[8];
    const int tid = threadIdx.x;
    double s = 0.0;
#pragma unroll
    for (int i = 0; i < 8; i++) s += (double)g_d2[tid + i * 256];
#pragma unroll
    for (int o = 16; o; o >>= 1) s += __shfl_down_sync(0xFFFFFFFFu, s, o);
    if ((tid & 31) == 0) red[tid >> 5] = s;
    __syncthreads();
    if (tid == 0) {
        double tot = g_acc;
#pragma unroll
        for (int w = 0; w < 8; w++) tot += red[w];
        out[0] = (float)(tot / (2.0 * (double)NROWS));
        g_acc = 0.0;   // self-reset: every kernel_launch call starts clean
        g_nflag = 0;
    }
}

extern "C" void kernel_launch(void* const* d_in, const int* in_sizes, int n_in,
                              void* d_out, int out_size) {
    (void)in_sizes; (void)n_in; (void)out_size;
    const float* C = (const float*)d_in[0];  // content_code
    const float* A = (const float*)d_in[1];  // audio_feature

    normalize_kernel<<<NROWS, 256>>>(C, A);
    screen_gemm_kernel<<<dim3(NROWS / TILE, NROWS / TILE), 256>>>();
    fallback_kernel<<<148, 256>>>(C, A);
    finalize_kernel<<<1, 256>>>((float*)d_out);
}

// round 5
// speedup vs baseline: 5.6378x; 1.3716x over previous
#include <cuda_runtime.h>
#include <cuda_bf16.h>
#include <cstdint>
#include <cstddef>

// ---------------------------------------------------------------------------
// ContentContrastiveLoss, GB300 (sm_103 target: mma.sync only, no tcgen05).
// Round 5: HEAD=512 CS screen, lean normalize, fused finalize.
//   loss = ( sum_offdiag max(0.2-||ci-aj||,0)^2 + sum_i ||ci-ai||^2 ) / (2N)
// Hinge active only if sim > 0.98. Cauchy-Schwarz screen:
//   sim <= head_dot(512) + rc_i*ra_j ; flag if bf16 bound > 0.97.
// Exact fp32 fallback for flagged pairs (expected none). Diagonal exact fp32,
// accumulated during normalize. Last fallback block finalizes + resets state.
// ---------------------------------------------------------------------------

#define NROWS 2048
#define DIM   8192
#define HEAD  512
#define TILE  128
#define KC    32          // bf16 K elems per GEMM chunk
#define SSTR  40          // smem row stride in bf16 elems (80B)
#define FCAP  65536

__device__ __nv_bfloat16 g_Ch[(size_t)NROWS * HEAD];  // normalized heads
__device__ __nv_bfloat16 g_Ah[(size_t)NROWS * HEAD];
__device__ float  g_rc[NROWS];      // tail-norm fraction of C rows
__device__ float  g_ra[NROWS];
__device__ float  g_invC[NROWS];    // 1/max(||c||,eps)
__device__ float  g_invA[NROWS];
__device__ int    g_nflag;          // flagged-pair count
__device__ int    g_done;           // fallback block completion counter
__device__ int2   g_flags[FCAP];
__device__ double g_acc;            // diag + hinge accumulator

__device__ __forceinline__ uint32_t smem_u32(const void* p) {
    return (uint32_t)__cvta_generic_to_shared(p);
}
__device__ __forceinline__ void cp_async16(uint32_t dst, const void* src) {
    asm volatile("cp.async.cg.shared.global [%0], [%1], 16;" :: "r"(dst), "l"(src));
}
__device__ __forceinline__ void cp_commit() { asm volatile("cp.async.commit_group;"); }
template <int N>
__device__ __forceinline__ void cp_wait() {
    asm volatile("cp.async.wait_group %0;" :: "n"(N));
}
__device__ __forceinline__ void ldsm_x4(uint32_t (&r)[4], uint32_t addr) {
    asm volatile("ldmatrix.sync.aligned.m8n8.x4.shared.b16 {%0,%1,%2,%3}, [%4];"
                 : "=r"(r[0]), "=r"(r[1]), "=r"(r[2]), "=r"(r[3]) : "r"(addr));
}
__device__ __forceinline__ void mma_bf16(float (&d)[4], const uint32_t (&a)[4],
                                         const uint32_t b0, const uint32_t b1) {
    asm volatile(
        "mma.sync.aligned.m16n8k16.row.col.f32.bf16.bf16.f32 "
        "{%0,%1,%2,%3}, {%4,%5,%6,%7}, {%8,%9}, {%0,%1,%2,%3};"
        : "+f"(d[0]), "+f"(d[1]), "+f"(d[2]), "+f"(d[3])
        : "r"(a[0]), "r"(a[1]), "r"(a[2]), "r"(a[3]), "r"(b0), "r"(b1));
}
__device__ __forceinline__ float dot4(const float4 a, const float4 b) {
    return a.x * b.x + a.y * b.y + a.z * b.z + a.w * b.w;
}

// ---------------------------------------------------------------------------
// Kernel 1: per-row: stream norms of C and A + exact fp32 diag dot; retain
// only head (512 elems); write bf16 heads + tail fractions; diag d2 -> g_acc.
// ---------------------------------------------------------------------------
__global__ void __launch_bounds__(256) normalize_kernel(
    const float* __restrict__ C, const float* __restrict__ A) {
    __shared__ float red[8][5];
    const int row = blockIdx.x;
    const int tid = threadIdx.x;

    const float4* cs = (const float4*)(C + (size_t)row * DIM);
    const float4* as = (const float4*)(A + (size_t)row * DIM);

    float4 ch = make_float4(0.f, 0.f, 0.f, 0.f);
    float4 ah = make_float4(0.f, 0.f, 0.f, 0.f);
    float sC = 0.f, sA = 0.f, sD = 0.f, hC = 0.f, hA = 0.f;
#pragma unroll
    for (int i = 0; i < 8; i++) {
        const float4 c = cs[tid + i * 256];
        const float4 a = as[tid + i * 256];
        sC += dot4(c, c);
        sA += dot4(a, a);
        sD += dot4(c, a);
        if (i == 0 && tid < (HEAD / 4)) {  // head = first 128 float4s
            ch = c; ah = a;
            hC = dot4(c, c); hA = dot4(a, a);
        }
    }

    float v5[5] = {sC, sA, sD, hC, hA};
#pragma unroll
    for (int j = 0; j < 5; j++)
#pragma unroll
        for (int o = 16; o; o >>= 1)
            v5[j] += __shfl_down_sync(0xFFFFFFFFu, v5[j], o);
    if ((tid & 31) == 0)
#pragma unroll
        for (int j = 0; j < 5; j++) red[tid >> 5][j] = v5[j];
    __syncthreads();
    float tC = 0.f, tA = 0.f, tD = 0.f, tHC = 0.f, tHA = 0.f;
#pragma unroll
    for (int w = 0; w < 8; w++) {
        tC += red[w][0]; tA += red[w][1]; tD += red[w][2];
        tHC += red[w][3]; tHA += red[w][4];
    }
    const float invC = 1.0f / fmaxf(sqrtf(tC), 1e-12f);
    const float invA = 1.0f / fmaxf(sqrtf(tA), 1e-12f);

    if (tid == 0) {
        const float sim = tD * invC * invA;
        const float d2  = fmaxf(2.0f - 2.0f * sim, 0.0f);
        atomicAdd(&g_acc, (double)d2);          // exact diagonal term
        g_invC[row] = invC;
        g_invA[row] = invA;
        g_rc[row] = sqrtf(fmaxf(1.0f - tHC * invC * invC, 0.0f));
        g_ra[row] = sqrtf(fmaxf(1.0f - tHA * invA * invA, 0.0f));
    }

    if (tid < (HEAD / 4)) {
        __nv_bfloat162 lo = __floats2bfloat162_rn(ch.x * invC, ch.y * invC);
        __nv_bfloat162 hi = __floats2bfloat162_rn(ch.z * invC, ch.w * invC);
        uint2 p;
        p.x = *reinterpret_cast<uint32_t*>(&lo);
        p.y = *reinterpret_cast<uint32_t*>(&hi);
        ((uint2*)(g_Ch + (size_t)row * HEAD))[tid] = p;

        lo = __floats2bfloat162_rn(ah.x * invA, ah.y * invA);
        hi = __floats2bfloat162_rn(ah.z * invA, ah.w * invA);
        p.x = *reinterpret_cast<uint32_t*>(&lo);
        p.y = *reinterpret_cast<uint32_t*>(&hi);
        ((uint2*)(g_Ah + (size_t)row * HEAD))[tid] = p;
    }
}

// ---------------------------------------------------------------------------
// Kernel 2: 128x128-tile bf16 HMMA screen GEMM over K=HEAD=512.
// ---------------------------------------------------------------------------
__global__ void __launch_bounds__(256) screen_gemm_kernel() {
    __shared__ __align__(16) __nv_bfloat16 sA[2][TILE * SSTR];
    __shared__ __align__(16) __nv_bfloat16 sB[2][TILE * SSTR];
    __shared__ float rcS[TILE], raS[TILE];

    const int tid    = threadIdx.x;
    const int wid    = tid >> 5;
    const int lane   = tid & 31;
    const int warp_m = wid & 3;
    const int warp_n = wid >> 2;

    const int ti = blockIdx.y;
    const int tj = blockIdx.x;
    const __nv_bfloat16* __restrict__ Ab = g_Ch + (size_t)ti * TILE * HEAD;
    const __nv_bfloat16* __restrict__ Bb = g_Ah + (size_t)tj * TILE * HEAD;

    // global->shared tasks: 2 tiles x 128 rows x 4 segs(16B) = 1024, 4/thread
    const __nv_bfloat16* t_src[4];
    uint32_t t_dst[4];
#pragma unroll
    for (int t = 0; t < 4; t++) {
        const int task  = tid + t * 256;
        const int which = task >> 9;
        const int r     = (task >> 2) & 127;
        const int seg   = task & 3;
        t_src[t] = (which ? Bb : Ab) + (size_t)r * HEAD + seg * 8;
        t_dst[t] = smem_u32((which ? &sB[0][0] : &sA[0][0]) + r * SSTR + seg * 8);
    }
    const uint32_t buf_bytes = TILE * SSTR * sizeof(__nv_bfloat16);

    uint32_t aAddr[2];
#pragma unroll
    for (int mf = 0; mf < 2; mf++) {
        const int r = warp_m * 32 + mf * 16 + (lane & 15);
        aAddr[mf] = smem_u32(&sA[0][0] + r * SSTR + (lane >> 4) * 8);
    }
    uint32_t bAddr[4];
#pragma unroll
    for (int p = 0; p < 4; p++) {
        const int r = warp_n * 64 + p * 16 + (lane & 7) + ((lane >> 4) & 1) * 8;
        bAddr[p] = smem_u32(&sB[0][0] + r * SSTR + ((lane >> 3) & 1) * 8);
    }

    float acc[2][8][4];
#pragma unroll
    for (int mf = 0; mf < 2; mf++)
#pragma unroll
        for (int nf = 0; nf < 8; nf++)
#pragma unroll
            for (int e = 0; e < 4; e++) acc[mf][nf][e] = 0.0f;

    if (tid < TILE) rcS[tid] = g_rc[ti * TILE + tid];
    else            raS[tid - TILE] = g_ra[tj * TILE + (tid - TILE)];

#pragma unroll
    for (int t = 0; t < 4; t++) cp_async16(t_dst[t], t_src[t]);
    cp_commit();

    const int NCHUNK = HEAD / KC;  // 16
    for (int k0 = 0; k0 < NCHUNK; k0++) {
        const uint32_t cur = (uint32_t)(k0 & 1) * buf_bytes;
        if (k0 + 1 < NCHUNK) {
            const uint32_t nxt = (uint32_t)((k0 + 1) & 1) * buf_bytes;
            const int koff = (k0 + 1) * KC;
#pragma unroll
            for (int t = 0; t < 4; t++) cp_async16(t_dst[t] + nxt, t_src[t] + koff);
            cp_commit();
            cp_wait<1>();
        } else {
            cp_wait<0>();
        }
        __syncthreads();

#pragma unroll
        for (int ks = 0; ks < 2; ks++) {
            uint32_t a[2][4];
#pragma unroll
            for (int mf = 0; mf < 2; mf++)
                ldsm_x4(a[mf], aAddr[mf] + cur + ks * 32);
            uint32_t b[8][2];
#pragma unroll
            for (int p = 0; p < 4; p++) {
                uint32_t r4[4];
                ldsm_x4(r4, bAddr[p] + cur + ks * 32);
                b[2 * p][0]     = r4[0];
                b[2 * p][1]     = r4[1];
                b[2 * p + 1][0] = r4[2];
                b[2 * p + 1][1] = r4[3];
            }
#pragma unroll
            for (int mf = 0; mf < 2; mf++)
#pragma unroll
                for (int nf = 0; nf < 8; nf++)
                    mma_bf16(acc[mf][nf], a[mf], b[nf][0], b[nf][1]);
        }
        __syncthreads();
    }

    // ---- screen: flag if CS upper bound can reach sim > 0.98 (0.01 slack) ----
#pragma unroll
    for (int mf = 0; mf < 2; mf++) {
#pragma unroll
        for (int nf = 0; nf < 8; nf++) {
#pragma unroll
            for (int e = 0; e < 4; e++) {
                const int li = warp_m * 32 + mf * 16 + (lane >> 2) + (e >> 1) * 8;
                const int lj = warp_n * 64 + nf * 8 + (lane & 3) * 2 + (e & 1);
                const int gi = ti * TILE + li;
                const int gj = tj * TILE + lj;
                if (gi == gj) continue;  // diagonal handled exactly elsewhere
                const float bound = acc[mf][nf][e] + rcS[li] * raS[lj];
                if (bound > 0.97f) {
                    const int idx = atomicAdd(&g_nflag, 1);
                    if (idx < FCAP) g_flags[idx] = make_int2(gi, gj);
                }
            }
        }
    }
}

// ---------------------------------------------------------------------------
// Kernel 3: exact fp32 hinge for flagged pairs (expected none); the LAST
// block to finish also finalizes the loss and resets state for graph replay.
// ---------------------------------------------------------------------------
__global__ void __launch_bounds__(256) fallback_kernel(
    const float* __restrict__ C, const float* __restrict__ A, float* out) {
    __shared__ float red[8];
    const int tid = threadIdx.x;
    const int total = min(g_nflag, FCAP);
    for (int p = blockIdx.x; p < total; p += gridDim.x) {
        const int2 pr = g_flags[p];
        const float4* c = (const float4*)(C + (size_t)pr.x * DIM);
        const float4* a = (const float4*)(A + (size_t)pr.y * DIM);
        float s = 0.f;
        for (int i = tid; i < DIM / 4; i += 256) s += dot4(c[i], a[i]);
#pragma unroll
        for (int o = 16; o; o >>= 1) s += __shfl_down_sync(0xFFFFFFFFu, s, o);
        if ((tid & 31) == 0) red[tid >> 5] = s;
        __syncthreads();
        if (tid == 0) {
            float tot = 0.f;
#pragma unroll
            for (int w = 0; w < 8; w++) tot += red[w];
            const float sim  = tot * g_invC[pr.x] * g_invA[pr.y];
            const float dist = sqrtf(fmaxf(2.0f - 2.0f * sim, 0.0f));
            const float diff = 0.2f - dist;
            if (diff > 0.0f) atomicAdd(&g_acc, (double)(diff * diff));
        }
        __syncthreads();
    }

    // last-done block finalizes and resets accumulators for the next replay
    if (tid == 0) {
        __threadfence();
        const int d = atomicAdd(&g_done, 1);
        if (d == (int)gridDim.x - 1) {
            const double tot = atomicAdd(&g_acc, 0.0);  // L2-coherent read
            out[0] = (float)(tot / (2.0 * (double)NROWS));
            g_acc   = 0.0;
            g_nflag = 0;
            g_done  = 0;
        }
    }
}

extern "C" void kernel_launch(void* const* d_in, const int* in_sizes, int n_in,
                              void* d_out, int out_size) {
    (void)in_sizes; (void)n_in; (void)out_size;
    const float* C = (const float*)d_in[0];  // content_code
    const float* A = (const float*)d_in[1];  // audio_feature

    normalize_kernel<<<NROWS, 256>>>(C, A);
    screen_gemm_kernel<<<dim3(NROWS / TILE, NROWS / TILE), 256>>>();
    fallback_kernel<<<148, 256>>>(C, A, (float*)d_out);
}